// round 8
// baseline (speedup 1.0000x reference)
#include <cuda_runtime.h>
#include <math.h>
#include <stddef.h>

#define BB 512
#define LL 100
#define EE 256
#define HH 256
#define TT 100
#define NG 1024  // 4*H

// ---------------- device scratch (no allocations allowed) ----------------
__device__ float d_eg[(size_t)BB * LL * HH];   // [b][l][h]  52.4 MB
__device__ float d_ep[(size_t)BB * LL * HH];   // [b][l][h]  52.4 MB
__device__ float d_x[BB * EE];
__device__ float d_h[BB * HH];
__device__ float d_c[BB * HH];
__device__ float d_g[BB * HH];
__device__ float d_qp[BB * HH];
__device__ float d_qpp[BB * HH];
__device__ float d_gates[BB * NG];
__device__ unsigned char d_mask[BB * LL];
__device__ int d_prev[BB];

__device__ __forceinline__ float sigf(float x) { return 1.f / (1.f + __expf(-x)); }
// accurate tanh (abs err ~1e-7), deterministic regardless of fast-math flags
__device__ __forceinline__ float tanh_acc(float x) {
    float a = fabsf(x);
    float e = __expf(-2.f * a);
    float t = (1.f - e) / (1.f + e);
    return (x < 0.f) ? -t : t;
}
__device__ __forceinline__ float neg_inf() { return __int_as_float(0xff800000); }

// ---------------- GEMM: C[M,N] = A[M,K] @ W[N,K]^T + bias ----------------
struct ADirect {
    const float* a; int ld;
    __device__ __forceinline__ float ld_(int r, int k) const { return a[(size_t)r * ld + k]; }
};
struct AConcat {  // A = [x | h], K = 512
    const float* x; const float* h;
    __device__ __forceinline__ float ld_(int r, int k) const {
        return (k < EE) ? x[r * EE + k] : h[r * HH + (k - EE)];
    }
};
struct ACtx {  // row r = (b*L + l)  ->  context[l, b, :]
    const float* c;
    __device__ __forceinline__ float ld_(int r, int k) const {
        int b = r / LL; int l = r - b * LL;
        return c[((size_t)l * BB + b) * HH + k];
    }
};
struct WDirect {
    const float* w; int ld;
    __device__ __forceinline__ float ld_(int n, int k) const { return w[(size_t)n * ld + k]; }
};
struct WConcat {  // W = [Wi | Wh], K = 512
    const float* w1; const float* w2;
    __device__ __forceinline__ float ld_(int n, int k) const {
        return (k < EE) ? w1[n * EE + k] : w2[n * HH + (k - EE)];
    }
};

template<int BM, int BN, int BK, int TM, int TN, class AT, class WT>
__global__ void gemm_kernel(AT A, WT W, const float* bias1, const float* bias2,
                            float* C, int M, int N, int K) {
    constexpr int THREADS = (BM / TM) * (BN / TN);
    constexpr int ASTR = BM + TM;  // pad keeps float4/float2 alignment, breaks bank conflicts
    constexpr int WSTR = BN + TN;
    constexpr int LA = BM * BK / THREADS;
    constexpr int LW = BN * BK / THREADS;
    __shared__ __align__(16) float As[2][BK * ASTR];
    __shared__ __align__(16) float Ws[2][BK * WSTR];

    int tid = threadIdx.x;
    int m0 = blockIdx.x * BM;
    int n0 = blockIdx.y * BN;
    int tn = tid % (BN / TN);
    int tm = tid / (BN / TN);
    int rm = tm * TM, rn = tn * TN;

    float acc[TM][TN] = {};
    float ra[LA], rw[LW];
    const int nt = K / BK;

    // prologue: load tile 0
#pragma unroll
    for (int i = 0; i < LA; i++) { int e = tid + i * THREADS; ra[i] = A.ld_(m0 + e / BK, e % BK); }
#pragma unroll
    for (int i = 0; i < LW; i++) { int e = tid + i * THREADS; rw[i] = W.ld_(n0 + e / BK, e % BK); }
#pragma unroll
    for (int i = 0; i < LA; i++) { int e = tid + i * THREADS; As[0][(e % BK) * ASTR + e / BK] = ra[i]; }
#pragma unroll
    for (int i = 0; i < LW; i++) { int e = tid + i * THREADS; Ws[0][(e % BK) * WSTR + e / BK] = rw[i]; }
    __syncthreads();

    int cur = 0;
    for (int t = 0; t < nt; t++) {
        int k0n = (t + 1) * BK;
        if (t + 1 < nt) {  // prefetch next tile into registers while computing
#pragma unroll
            for (int i = 0; i < LA; i++) { int e = tid + i * THREADS; ra[i] = A.ld_(m0 + e / BK, k0n + e % BK); }
#pragma unroll
            for (int i = 0; i < LW; i++) { int e = tid + i * THREADS; rw[i] = W.ld_(n0 + e / BK, k0n + e % BK); }
        }
#pragma unroll
        for (int k = 0; k < BK; k++) {
            float fa[TM], fb[TN];
            if constexpr (TM == 4) {
                float4 v = *reinterpret_cast<const float4*>(&As[cur][k * ASTR + rm]);
                fa[0] = v.x; fa[1] = v.y; fa[2] = v.z; fa[3] = v.w;
            } else {
                float2 v = *reinterpret_cast<const float2*>(&As[cur][k * ASTR + rm]);
                fa[0] = v.x; fa[1] = v.y;
            }
            if constexpr (TN == 4) {
                float4 v = *reinterpret_cast<const float4*>(&Ws[cur][k * WSTR + rn]);
                fb[0] = v.x; fb[1] = v.y; fb[2] = v.z; fb[3] = v.w;
            } else {
                float2 v = *reinterpret_cast<const float2*>(&Ws[cur][k * WSTR + rn]);
                fb[0] = v.x; fb[1] = v.y;
            }
#pragma unroll
            for (int i = 0; i < TM; i++)
#pragma unroll
                for (int j = 0; j < TN; j++)
                    acc[i][j] += fa[i] * fb[j];
        }
        if (t + 1 < nt) {
#pragma unroll
            for (int i = 0; i < LA; i++) { int e = tid + i * THREADS; As[cur ^ 1][(e % BK) * ASTR + e / BK] = ra[i]; }
#pragma unroll
            for (int i = 0; i < LW; i++) { int e = tid + i * THREADS; Ws[cur ^ 1][(e % BK) * WSTR + e / BK] = rw[i]; }
        }
        __syncthreads();
        cur ^= 1;
    }

#pragma unroll
    for (int j = 0; j < TN; j++) {
        int n = n0 + rn + j;
        float bsum = 0.f;
        if (bias1) bsum += bias1[n];
        if (bias2) bsum += bias2[n];
#pragma unroll
        for (int i = 0; i < TM; i++) {
            int m = m0 + rm + i;
            C[(size_t)m * N + n] = acc[i][j] + bsum;
        }
    }
}

// ---------------- init ----------------
__global__ void init_kernel(const float* dec, const float* h0, const float* c0) {
    int i = blockIdx.x * blockDim.x + threadIdx.x;
    if (i < BB * EE) d_x[i] = dec[i];
    if (i < BB * HH) { d_h[i] = h0[i]; d_c[i] = c0[i]; }
    if (i < BB * LL) d_mask[i] = 0;
    if (i < BB) d_prev[i] = 0;
}

// ---------------- LSTM elementwise ----------------
__global__ void lstm_kernel() {
    int i = blockIdx.x * 256 + threadIdx.x;  // over B*H
    int b = i >> 8, h = i & 255;
    const float* g = d_gates + (size_t)b * NG;
    float ig = g[h], fg = g[HH + h], cg = g[2 * HH + h], og = g[3 * HH + h];
    float c = sigf(fg) * d_c[i] + sigf(ig) * tanh_acc(cg);
    float hy = sigf(og) * tanh_acc(c);
    d_c[i] = c;
    d_h[i] = hy;
}

// ---------------- glimpse: mask update + logits + softmax + readout ----------------
__global__ void glimpse_kernel(int step, const float* __restrict__ gv) {
    int b = blockIdx.x;
    int tid = threadIdx.x;  // 256
    __shared__ float qs[HH], vs[HH], lg[LL], ws[LL];
    __shared__ unsigned char ms[LL];

    qs[tid] = d_qp[(size_t)b * HH + tid];
    vs[tid] = gv[tid];
    if (tid < LL) ms[tid] = d_mask[b * LL + tid];
    __syncthreads();
    if (tid == 0) {
        if (step == 0) ms[0] = 1;
        else { if (step == 1) ms[0] = 0; ms[d_prev[b]] = 1; }
    }
    __syncthreads();
    if (tid < LL) d_mask[b * LL + tid] = ms[tid];

    int warp = tid >> 5, lane = tid & 31;
    const float* eb = d_eg + (size_t)b * LL * HH;
    for (int l = warp; l < LL; l += 8) {
        const float* er = eb + (size_t)l * HH;
        float acc = 0.f;
#pragma unroll
        for (int i = 0; i < 8; i++) {
            int h = lane + i * 32;
            acc += vs[h] * tanh_acc(qs[h] + er[h]);
        }
#pragma unroll
        for (int o = 16; o; o >>= 1) acc += __shfl_xor_sync(0xffffffffu, acc, o);
        if (lane == 0) lg[l] = ms[l] ? neg_inf() : acc;
    }
    __syncthreads();

    if (warp == 0) {  // masked softmax over L=100
        float v[4]; float mx = neg_inf();
#pragma unroll
        for (int i = 0; i < 4; i++) {
            int l = lane + i * 32;
            v[i] = (l < LL) ? lg[l] : neg_inf();
            mx = fmaxf(mx, v[i]);
        }
#pragma unroll
        for (int o = 16; o; o >>= 1) mx = fmaxf(mx, __shfl_xor_sync(0xffffffffu, mx, o));
        float s = 0.f;
#pragma unroll
        for (int i = 0; i < 4; i++) { v[i] = __expf(v[i] - mx); s += v[i]; }
#pragma unroll
        for (int o = 16; o; o >>= 1) s += __shfl_xor_sync(0xffffffffu, s, o);
#pragma unroll
        for (int i = 0; i < 4; i++) {
            int l = lane + i * 32;
            if (l < LL) ws[l] = v[i] / s;
        }
    }
    __syncthreads();

    // readout g[b,h] = sum_l e_g[b,l,h] * w[l]
    float g = 0.f;
#pragma unroll 4
    for (int l = 0; l < LL; l++) g += ws[l] * eb[(size_t)l * HH + tid];
    d_g[(size_t)b * HH + tid] = g;
}

// ---------------- pointer: logits + mask + softmax + argmax + select ----------------
__global__ void pointer_kernel(int step, const float* __restrict__ pv,
                               const float* __restrict__ emb,
                               float* __restrict__ out_probs,
                               float* __restrict__ out_sel) {
    int b = blockIdx.x;
    int tid = threadIdx.x;  // 256
    __shared__ float qs[HH], vs[HH], lp[LL], ps[LL];
    __shared__ unsigned char ms[LL];
    __shared__ int sidx;

    qs[tid] = d_qpp[(size_t)b * HH + tid];
    vs[tid] = pv[tid];
    if (tid < LL) ms[tid] = d_mask[b * LL + tid];  // already updated this step
    __syncthreads();

    int warp = tid >> 5, lane = tid & 31;
    const float* eb = d_ep + (size_t)b * LL * HH;
    for (int l = warp; l < LL; l += 8) {
        const float* er = eb + (size_t)l * HH;
        float acc = 0.f;
#pragma unroll
        for (int i = 0; i < 8; i++) {
            int h = lane + i * 32;
            acc += vs[h] * tanh_acc(qs[h] + er[h]);
        }
#pragma unroll
        for (int o = 16; o; o >>= 1) acc += __shfl_xor_sync(0xffffffffu, acc, o);
        if (lane == 0) lp[l] = ms[l] ? neg_inf() : (10.0f * tanh_acc(acc));
    }
    __syncthreads();

    if (warp == 0) {
        float v[4]; float mx = neg_inf();
#pragma unroll
        for (int i = 0; i < 4; i++) {
            int l = lane + i * 32;
            v[i] = (l < LL) ? lp[l] : neg_inf();
            mx = fmaxf(mx, v[i]);
        }
#pragma unroll
        for (int o = 16; o; o >>= 1) mx = fmaxf(mx, __shfl_xor_sync(0xffffffffu, mx, o));
        float s = 0.f;
#pragma unroll
        for (int i = 0; i < 4; i++) { v[i] = __expf(v[i] - mx); s += v[i]; }
#pragma unroll
        for (int o = 16; o; o >>= 1) s += __shfl_xor_sync(0xffffffffu, s, o);
        float bv = -1.f; int bi = 0;
#pragma unroll
        for (int i = 0; i < 4; i++) {
            int l = lane + i * 32;
            if (l < LL) {
                float p = v[i] / s;
                ps[l] = p;
                if (p > bv) { bv = p; bi = l; }  // increasing l -> first occurrence within lane
            }
        }
        // cross-lane argmax, tie-break to smaller index (jnp.argmax semantics)
#pragma unroll
        for (int o = 16; o; o >>= 1) {
            float ov = __shfl_xor_sync(0xffffffffu, bv, o);
            int oi = __shfl_xor_sync(0xffffffffu, bi, o);
            if (ov > bv || (ov == bv && oi < bi)) { bv = ov; bi = oi; }
        }
        if (lane == 0) {
            sidx = bi;
            d_prev[b] = bi;
            out_sel[(size_t)step * BB + b] = (float)bi;
        }
    }
    __syncthreads();

    if (tid < LL) out_probs[((size_t)step * BB + b) * LL + tid] = ps[tid];
    // next decoder input: x[b,:] = embedded_inputs[idx, b, :]
    d_x[(size_t)b * EE + tid] = emb[((size_t)sidx * BB + b) * EE + tid];
}

// ---------------- finalize: hx, cx tails ----------------
__global__ void finalize_kernel(float* out) {
    int i = blockIdx.x * 256 + threadIdx.x;
    if (i < BB * HH) {
        size_t base = (size_t)TT * BB * LL + (size_t)TT * BB;
        out[base + i] = d_h[i];
        out[base + (size_t)BB * HH + i] = d_c[i];
    }
}

// ---------------- launch ----------------
extern "C" void kernel_launch(void* const* d_in, const int* in_sizes, int n_in,
                              void* d_out, int out_size) {
    (void)out_size;

    // ---- resolve REAL device addresses of __device__ globals (host shadow
    // symbols are NOT device pointers — the round-7 bug). Host-side query,
    // graph-capture safe (adds no nodes).
    float *p_eg, *p_ep, *p_x, *p_h, *p_g, *p_qp, *p_qpp, *p_gates;
    cudaGetSymbolAddress((void**)&p_eg, d_eg);
    cudaGetSymbolAddress((void**)&p_ep, d_ep);
    cudaGetSymbolAddress((void**)&p_x, d_x);
    cudaGetSymbolAddress((void**)&p_h, d_h);
    cudaGetSymbolAddress((void**)&p_g, d_g);
    cudaGetSymbolAddress((void**)&p_qp, d_qp);
    cudaGetSymbolAddress((void**)&p_qpp, d_qpp);
    cudaGetSymbolAddress((void**)&p_gates, d_gates);

    // ---- input-order detection: dict order (expected) vs alphabetical fallback
    static const int sig_dict[19] = {131072, 13107200, 131072, 131072, 13107200,
                                     262144, 1024, 262144, 1024, 65536, 256,
                                     65536, 256, 256, 65536, 256, 65536, 256, 256};
    // map[logical] = physical index under alphabetical key order
    static const int alpha_map[19] = {6, 7, 13, 4, 5, 1, 3, 0, 2, 8, 10, 9, 11, 12, 14, 16, 15, 17, 18};
    bool dict_ok = (n_in == 19);
    if (dict_ok) for (int i = 0; i < 19; i++) if (in_sizes[i] != sig_dict[i]) { dict_ok = false; break; }
    const float* in[19];
    for (int i = 0; i < 19; i++)
        in[i] = (const float*)d_in[dict_ok ? i : alpha_map[i]];

    const float* dec   = in[0];
    const float* emb   = in[1];
    const float* h0    = in[2];
    const float* c0    = in[3];
    const float* ctx   = in[4];
    const float* Wi    = in[5];
    const float* bi    = in[6];
    const float* Wh    = in[7];
    const float* bh    = in[8];
    const float* gWq   = in[9];
    const float* gbq   = in[10];
    const float* gWref = in[11];
    const float* gbref = in[12];
    const float* gv    = in[13];
    const float* pWq   = in[14];
    const float* pbq   = in[15];
    const float* pWref = in[16];
    const float* pbref = in[17];
    const float* pv    = in[18];

    float* out = (float*)d_out;
    float* out_probs = out;                               // T*B*L
    float* out_sel   = out + (size_t)TT * BB * LL;        // T*B

    init_kernel<<<(BB * EE + 255) / 256, 256>>>(dec, h0, c0);

    // one-time: e_g / e_p  (M=51200, N=256, K=256)
    {
        ACtx a{ctx};
        WDirect wg{gWref, HH};
        gemm_kernel<64, 64, 16, 4, 4><<<dim3(BB * LL / 64, HH / 64), 256>>>(
            a, wg, gbref, nullptr, p_eg, BB * LL, HH, HH);
        WDirect wp{pWref, HH};
        gemm_kernel<64, 64, 16, 4, 4><<<dim3(BB * LL / 64, HH / 64), 256>>>(
            a, wp, pbref, nullptr, p_ep, BB * LL, HH, HH);
    }

    for (int t = 0; t < TT; t++) {
        // gates = [x|h] @ [Wi|Wh]^T + (bi + bh)   (M=512, N=1024, K=512)
        AConcat ax{p_x, p_h};
        WConcat wc{Wi, Wh};
        gemm_kernel<64, 64, 16, 4, 4><<<dim3(BB / 64, NG / 64), 256>>>(
            ax, wc, bi, bh, p_gates, BB, NG, EE + HH);

        lstm_kernel<<<BB * HH / 256, 256>>>();

        // qp_g = hy @ g_Wq^T + g_bq
        {
            ADirect ah{p_h, HH};
            WDirect wq{gWq, HH};
            gemm_kernel<32, 32, 16, 2, 2><<<dim3(BB / 32, HH / 32), 256>>>(
                ah, wq, gbq, nullptr, p_qp, BB, HH, HH);
        }

        glimpse_kernel<<<BB, 256>>>(t, gv);

        // qp_p = g @ p_Wq^T + p_bq
        {
            ADirect ag{p_g, HH};
            WDirect wq{pWq, HH};
            gemm_kernel<32, 32, 16, 2, 2><<<dim3(BB / 32, HH / 32), 256>>>(
                ag, wq, pbq, nullptr, p_qpp, BB, HH, HH);
        }

        pointer_kernel<<<BB, 256>>>(t, pv, emb, out_probs, out_sel);
    }

    finalize_kernel<<<(BB * HH + 255) / 256, 256>>>(out);
}

// round 9
// speedup vs baseline: 2.4833x; 2.4833x over previous
#include <cuda_runtime.h>
#include <math.h>
#include <stddef.h>

#define BB 512
#define LL 100
#define EE 256
#define HH 256
#define TT 100
#define NG 1024  // 4*H

// ---------------- device scratch (no allocations allowed) ----------------
__device__ float d_eg[(size_t)BB * LL * HH];   // [b][l][h]  52.4 MB
__device__ float d_ep[(size_t)BB * LL * HH];   // [b][l][h]  52.4 MB
__device__ float d_x[BB * EE];
__device__ float d_h0b[BB * HH];
__device__ float d_h1b[BB * HH];
__device__ float d_c0b[BB * HH];
__device__ float d_c1b[BB * HH];
__device__ unsigned char d_mask[BB * LL];
__device__ int d_prev[BB];

__device__ __forceinline__ float sigf(float x) { return __fdividef(1.f, 1.f + __expf(-x)); }
// tanh via exp + fast divide (rel err ~2^-22)
__device__ __forceinline__ float tanh_fast(float x) {
    float a = fabsf(x);
    float e = __expf(-2.f * a);
    float t = __fdividef(1.f - e, 1.f + e);
    return (x < 0.f) ? -t : t;
}
__device__ __forceinline__ float neg_inf() { return __int_as_float(0xff800000); }

// ================= one-time GEMM: C[M,N] = A[M,K] @ W[N,K]^T + bias ==========
struct ACtx {  // row r = (b*L + l)  ->  context[l, b, :]
    const float* c;
    __device__ __forceinline__ float ld_(int r, int k) const {
        int b = r / LL; int l = r - b * LL;
        return c[((size_t)l * BB + b) * HH + k];
    }
};
struct WDirect {
    const float* w; int ld;
    __device__ __forceinline__ float ld_(int n, int k) const { return w[(size_t)n * ld + k]; }
};

template<int BM, int BN, int BK, int TM, int TN, class AT, class WT>
__global__ void gemm_kernel(AT A, WT W, const float* bias1,
                            float* C, int M, int N, int K) {
    constexpr int THREADS = (BM / TM) * (BN / TN);
    constexpr int ASTR = BM + TM;
    constexpr int WSTR = BN + TN;
    constexpr int LA = BM * BK / THREADS;
    constexpr int LW = BN * BK / THREADS;
    __shared__ __align__(16) float As[2][BK * ASTR];
    __shared__ __align__(16) float Ws[2][BK * WSTR];

    int tid = threadIdx.x;
    int m0 = blockIdx.x * BM;
    int n0 = blockIdx.y * BN;
    int tn = tid % (BN / TN);
    int tm = tid / (BN / TN);
    int rm = tm * TM, rn = tn * TN;

    float acc[TM][TN] = {};
    float ra[LA], rw[LW];
    const int nt = K / BK;

#pragma unroll
    for (int i = 0; i < LA; i++) { int e = tid + i * THREADS; ra[i] = A.ld_(m0 + e / BK, e % BK); }
#pragma unroll
    for (int i = 0; i < LW; i++) { int e = tid + i * THREADS; rw[i] = W.ld_(n0 + e / BK, e % BK); }
#pragma unroll
    for (int i = 0; i < LA; i++) { int e = tid + i * THREADS; As[0][(e % BK) * ASTR + e / BK] = ra[i]; }
#pragma unroll
    for (int i = 0; i < LW; i++) { int e = tid + i * THREADS; Ws[0][(e % BK) * WSTR + e / BK] = rw[i]; }
    __syncthreads();

    int cur = 0;
    for (int t = 0; t < nt; t++) {
        int k0n = (t + 1) * BK;
        if (t + 1 < nt) {
#pragma unroll
            for (int i = 0; i < LA; i++) { int e = tid + i * THREADS; ra[i] = A.ld_(m0 + e / BK, k0n + e % BK); }
#pragma unroll
            for (int i = 0; i < LW; i++) { int e = tid + i * THREADS; rw[i] = W.ld_(n0 + e / BK, k0n + e % BK); }
        }
#pragma unroll
        for (int k = 0; k < BK; k++) {
            float4 va = *reinterpret_cast<const float4*>(&As[cur][k * ASTR + rm]);
            float4 vb = *reinterpret_cast<const float4*>(&Ws[cur][k * WSTR + rn]);
            float fa[4] = {va.x, va.y, va.z, va.w};
            float fb[4] = {vb.x, vb.y, vb.z, vb.w};
#pragma unroll
            for (int i = 0; i < TM; i++)
#pragma unroll
                for (int j = 0; j < TN; j++)
                    acc[i][j] += fa[i] * fb[j];
        }
        if (t + 1 < nt) {
#pragma unroll
            for (int i = 0; i < LA; i++) { int e = tid + i * THREADS; As[cur ^ 1][(e % BK) * ASTR + e / BK] = ra[i]; }
#pragma unroll
            for (int i = 0; i < LW; i++) { int e = tid + i * THREADS; Ws[cur ^ 1][(e % BK) * WSTR + e / BK] = rw[i]; }
        }
        __syncthreads();
        cur ^= 1;
    }

#pragma unroll
    for (int j = 0; j < TN; j++) {
        int n = n0 + rn + j;
        float bsum = bias1 ? bias1[n] : 0.f;
#pragma unroll
        for (int i = 0; i < TM; i++) {
            int m = m0 + rm + i;
            C[(size_t)m * N + n] = acc[i][j] + bsum;
        }
    }
}

// ============ fused gates GEMM + LSTM epilogue ============
// C columns interleaved: n = 4*h + g  (g = gate 0..3 = i,f,c,o)
// so each thread's TN=4 columns are the 4 gates of a single h.
__global__ void gates_lstm_kernel(const float* __restrict__ x,
                                  const float* __restrict__ h_in,
                                  const float* __restrict__ Wi,
                                  const float* __restrict__ Wh,
                                  const float* __restrict__ bi,
                                  const float* __restrict__ bh,
                                  const float* __restrict__ c_in,
                                  float* __restrict__ c_out,
                                  float* __restrict__ h_out) {
    constexpr int BM = 32, BN = 64, BK = 16, TM = 2, TN = 4, THREADS = 256;
    constexpr int ASTR = BM + 2, WSTR = BN + 4;
    constexpr int KK = EE + HH;  // 512
    __shared__ __align__(16) float As[2][BK * ASTR];
    __shared__ __align__(16) float Ws[2][BK * WSTR];

    int tid = threadIdx.x;
    int m0 = blockIdx.x * BM;
    int n0 = blockIdx.y * BN;
    int tn = tid % (BN / TN);   // 16
    int tm = tid / (BN / TN);   // 16
    int rm = tm * TM, rn = tn * TN;

    auto ldA = [&](int r, int k) -> float {
        return (k < EE) ? x[r * EE + k] : h_in[r * HH + (k - EE)];
    };
    auto ldW = [&](int n, int k) -> float {
        int g = n & 3, h = n >> 2;
        int row = g * HH + h;
        return (k < EE) ? Wi[row * EE + k] : Wh[row * HH + (k - EE)];
    };

    float acc[TM][TN] = {};
    float ra[2], rw[4];
    const int nt = KK / BK;  // 32

#pragma unroll
    for (int i = 0; i < 2; i++) { int e = tid + i * THREADS; ra[i] = ldA(m0 + e / BK, e % BK); }
#pragma unroll
    for (int i = 0; i < 4; i++) { int e = tid + i * THREADS; rw[i] = ldW(n0 + e / BK, e % BK); }
#pragma unroll
    for (int i = 0; i < 2; i++) { int e = tid + i * THREADS; As[0][(e % BK) * ASTR + e / BK] = ra[i]; }
#pragma unroll
    for (int i = 0; i < 4; i++) { int e = tid + i * THREADS; Ws[0][(e % BK) * WSTR + e / BK] = rw[i]; }
    __syncthreads();

    int cur = 0;
    for (int t = 0; t < nt; t++) {
        int k0n = (t + 1) * BK;
        if (t + 1 < nt) {
#pragma unroll
            for (int i = 0; i < 2; i++) { int e = tid + i * THREADS; ra[i] = ldA(m0 + e / BK, k0n + e % BK); }
#pragma unroll
            for (int i = 0; i < 4; i++) { int e = tid + i * THREADS; rw[i] = ldW(n0 + e / BK, k0n + e % BK); }
        }
#pragma unroll
        for (int k = 0; k < BK; k++) {
            float2 va = *reinterpret_cast<const float2*>(&As[cur][k * ASTR + rm]);
            float4 vb = *reinterpret_cast<const float4*>(&Ws[cur][k * WSTR + rn]);
            float fa[2] = {va.x, va.y};
            float fb[4] = {vb.x, vb.y, vb.z, vb.w};
#pragma unroll
            for (int i = 0; i < TM; i++)
#pragma unroll
                for (int j = 0; j < TN; j++)
                    acc[i][j] += fa[i] * fb[j];
        }
        if (t + 1 < nt) {
#pragma unroll
            for (int i = 0; i < 2; i++) { int e = tid + i * THREADS; As[cur ^ 1][(e % BK) * ASTR + e / BK] = ra[i]; }
#pragma unroll
            for (int i = 0; i < 4; i++) { int e = tid + i * THREADS; Ws[cur ^ 1][(e % BK) * WSTR + e / BK] = rw[i]; }
        }
        __syncthreads();
        cur ^= 1;
    }

    // LSTM epilogue: this thread holds gates i,f,c,o of column h for TM rows
    int h = (n0 + rn) >> 2;
    float b0 = bi[0 * HH + h] + bh[0 * HH + h];
    float b1 = bi[1 * HH + h] + bh[1 * HH + h];
    float b2 = bi[2 * HH + h] + bh[2 * HH + h];
    float b3 = bi[3 * HH + h] + bh[3 * HH + h];
#pragma unroll
    for (int i = 0; i < TM; i++) {
        int m = m0 + rm + i;
        float ig = acc[i][0] + b0;
        float fg = acc[i][1] + b1;
        float cg = acc[i][2] + b2;
        float og = acc[i][3] + b3;
        float cy = sigf(fg) * c_in[m * HH + h] + sigf(ig) * tanh_fast(cg);
        c_out[m * HH + h] = cy;
        h_out[m * HH + h] = sigf(og) * tanh_fast(cy);
    }
}

// ---------------- init ----------------
__global__ void init_kernel(const float* dec, const float* h0, const float* c0) {
    int i = blockIdx.x * blockDim.x + threadIdx.x;
    if (i < BB * EE) d_x[i] = dec[i];
    if (i < BB * HH) { d_h0b[i] = h0[i]; d_c0b[i] = c0[i]; }
    if (i < BB * LL) d_mask[i] = 0;
    if (i < BB) d_prev[i] = 0;
}

// ============ attention megakernel (one block per batch row b) ============
// phases: mask update -> qp proj -> glimpse logits/softmax/readout ->
//         qpp proj -> pointer logits/softmax/argmax -> select
__global__ void attn_kernel(int step,
                            const float* __restrict__ hnew,
                            const float* __restrict__ gWq, const float* __restrict__ gbq,
                            const float* __restrict__ gv,
                            const float* __restrict__ pWq, const float* __restrict__ pbq,
                            const float* __restrict__ pv,
                            const float* __restrict__ emb,
                            float* __restrict__ out_probs,
                            float* __restrict__ out_sel,
                            float* __restrict__ x_out) {
    int b = blockIdx.x;
    int tid = threadIdx.x;  // 256
    int warp = tid >> 5, lane = tid & 31;
    __shared__ __align__(16) float hs[HH], qs[HH], vs[HH], gs[HH];
    __shared__ float lg[LL], ws[LL];
    __shared__ unsigned char ms[LL];
    __shared__ int sidx;

    // load h, gv, mask
    hs[tid] = hnew[(size_t)b * HH + tid];
    vs[tid] = gv[tid];
    if (tid < LL) ms[tid] = d_mask[b * LL + tid];
    __syncthreads();
    if (tid == 0) {
        if (step == 0) ms[0] = 1;
        else { if (step == 1) ms[0] = 0; ms[d_prev[b]] = 1; }
    }
    __syncthreads();
    if (tid < LL) d_mask[b * LL + tid] = ms[tid];

    const float4* hs4 = reinterpret_cast<const float4*>(hs);
    const float4* qs4 = reinterpret_cast<const float4*>(qs);
    const float4* vs4 = reinterpret_cast<const float4*>(vs);
    const float4* gs4 = reinterpret_cast<const float4*>(gs);

    // ---- qp = hnew @ gWq^T + gbq : warp w computes rows [32w, 32w+32)
    {
        const float4* W4 = reinterpret_cast<const float4*>(gWq);
        float4 a0 = hs4[lane], a1 = hs4[lane + 32];
        for (int r = 0; r < 32; r++) {
            int o = warp * 32 + r;
            float4 w0 = W4[(size_t)o * 64 + lane];
            float4 w1 = W4[(size_t)o * 64 + 32 + lane];
            float acc = w0.x * a0.x + w0.y * a0.y + w0.z * a0.z + w0.w * a0.w
                      + w1.x * a1.x + w1.y * a1.y + w1.z * a1.z + w1.w * a1.w;
#pragma unroll
            for (int off = 16; off; off >>= 1) acc += __shfl_xor_sync(0xffffffffu, acc, off);
            if (lane == 0) qs[o] = acc + gbq[o];
        }
    }
    __syncthreads();

    // ---- glimpse logits
    {
        float4 q0 = qs4[lane], q1 = qs4[lane + 32];
        float4 v0 = vs4[lane], v1 = vs4[lane + 32];
        const float4* eb4 = reinterpret_cast<const float4*>(d_eg + (size_t)b * LL * HH);
        for (int l = warp; l < LL; l += 8) {
            float4 e0 = eb4[(size_t)l * 64 + lane];
            float4 e1 = eb4[(size_t)l * 64 + 32 + lane];
            float acc = v0.x * tanh_fast(q0.x + e0.x) + v0.y * tanh_fast(q0.y + e0.y)
                      + v0.z * tanh_fast(q0.z + e0.z) + v0.w * tanh_fast(q0.w + e0.w)
                      + v1.x * tanh_fast(q1.x + e1.x) + v1.y * tanh_fast(q1.y + e1.y)
                      + v1.z * tanh_fast(q1.z + e1.z) + v1.w * tanh_fast(q1.w + e1.w);
#pragma unroll
            for (int off = 16; off; off >>= 1) acc += __shfl_xor_sync(0xffffffffu, acc, off);
            if (lane == 0) lg[l] = ms[l] ? neg_inf() : acc;
        }
    }
    __syncthreads();

    // ---- glimpse softmax (warp 0)
    if (warp == 0) {
        float v[4]; float mx = neg_inf();
#pragma unroll
        for (int i = 0; i < 4; i++) {
            int l = lane + i * 32;
            v[i] = (l < LL) ? lg[l] : neg_inf();
            mx = fmaxf(mx, v[i]);
        }
#pragma unroll
        for (int o = 16; o; o >>= 1) mx = fmaxf(mx, __shfl_xor_sync(0xffffffffu, mx, o));
        float s = 0.f;
#pragma unroll
        for (int i = 0; i < 4; i++) { v[i] = __expf(v[i] - mx); s += v[i]; }
#pragma unroll
        for (int o = 16; o; o >>= 1) s += __shfl_xor_sync(0xffffffffu, s, o);
        float inv = __fdividef(1.f, s);
#pragma unroll
        for (int i = 0; i < 4; i++) {
            int l = lane + i * 32;
            if (l < LL) ws[l] = v[i] * inv;
        }
    }
    __syncthreads();

    // ---- readout g[h] = sum_l ws[l] * e_g[b,l,h]
    {
        const float* eb = d_eg + (size_t)b * LL * HH;
        float g = 0.f;
#pragma unroll 4
        for (int l = 0; l < LL; l++) g += ws[l] * eb[(size_t)l * HH + tid];
        gs[tid] = g;
        vs[tid] = pv[tid];  // swap in pointer v for the next logits pass
    }
    __syncthreads();

    // ---- qpp = g @ pWq^T + pbq
    {
        const float4* W4 = reinterpret_cast<const float4*>(pWq);
        float4 a0 = gs4[lane], a1 = gs4[lane + 32];
        for (int r = 0; r < 32; r++) {
            int o = warp * 32 + r;
            float4 w0 = W4[(size_t)o * 64 + lane];
            float4 w1 = W4[(size_t)o * 64 + 32 + lane];
            float acc = w0.x * a0.x + w0.y * a0.y + w0.z * a0.z + w0.w * a0.w
                      + w1.x * a1.x + w1.y * a1.y + w1.z * a1.z + w1.w * a1.w;
#pragma unroll
            for (int off = 16; off; off >>= 1) acc += __shfl_xor_sync(0xffffffffu, acc, off);
            if (lane == 0) qs[o] = acc + pbq[o];
        }
    }
    __syncthreads();

    // ---- pointer logits
    {
        float4 q0 = qs4[lane], q1 = qs4[lane + 32];
        float4 v0 = vs4[lane], v1 = vs4[lane + 32];
        const float4* eb4 = reinterpret_cast<const float4*>(d_ep + (size_t)b * LL * HH);
        for (int l = warp; l < LL; l += 8) {
            float4 e0 = eb4[(size_t)l * 64 + lane];
            float4 e1 = eb4[(size_t)l * 64 + 32 + lane];
            float acc = v0.x * tanh_fast(q0.x + e0.x) + v0.y * tanh_fast(q0.y + e0.y)
                      + v0.z * tanh_fast(q0.z + e0.z) + v0.w * tanh_fast(q0.w + e0.w)
                      + v1.x * tanh_fast(q1.x + e1.x) + v1.y * tanh_fast(q1.y + e1.y)
                      + v1.z * tanh_fast(q1.z + e1.z) + v1.w * tanh_fast(q1.w + e1.w);
#pragma unroll
            for (int off = 16; off; off >>= 1) acc += __shfl_xor_sync(0xffffffffu, acc, off);
            if (lane == 0) lg[l] = ms[l] ? neg_inf() : (10.0f * tanh_fast(acc));
        }
    }
    __syncthreads();

    // ---- pointer softmax + argmax (warp 0), jnp first-occurrence tie-break
    if (warp == 0) {
        float v[4]; float mx = neg_inf();
#pragma unroll
        for (int i = 0; i < 4; i++) {
            int l = lane + i * 32;
            v[i] = (l < LL) ? lg[l] : neg_inf();
            mx = fmaxf(mx, v[i]);
        }
#pragma unroll
        for (int o = 16; o; o >>= 1) mx = fmaxf(mx, __shfl_xor_sync(0xffffffffu, mx, o));
        float s = 0.f;
#pragma unroll
        for (int i = 0; i < 4; i++) { v[i] = __expf(v[i] - mx); s += v[i]; }
#pragma unroll
        for (int o = 16; o; o >>= 1) s += __shfl_xor_sync(0xffffffffu, s, o);
        float inv = __fdividef(1.f, s);
        float bv = -1.f; int bi_ = 0;
#pragma unroll
        for (int i = 0; i < 4; i++) {
            int l = lane + i * 32;
            if (l < LL) {
                float p = v[i] * inv;
                ws[l] = p;
                if (p > bv) { bv = p; bi_ = l; }
            }
        }
#pragma unroll
        for (int o = 16; o; o >>= 1) {
            float ov = __shfl_xor_sync(0xffffffffu, bv, o);
            int oi = __shfl_xor_sync(0xffffffffu, bi_, o);
            if (ov > bv || (ov == bv && oi < bi_)) { bv = ov; bi_ = oi; }
        }
        if (lane == 0) {
            sidx = bi_;
            d_prev[b] = bi_;
            out_sel[(size_t)step * BB + b] = (float)bi_;
        }
    }
    __syncthreads();

    if (tid < LL) out_probs[((size_t)step * BB + b) * LL + tid] = ws[tid];
    x_out[(size_t)b * EE + tid] = emb[((size_t)sidx * BB + b) * EE + tid];
}

// ---------------- finalize: hx, cx tails ----------------
__global__ void finalize_kernel(const float* hfin, const float* cfin, float* out) {
    int i = blockIdx.x * 256 + threadIdx.x;
    if (i < BB * HH) {
        size_t base = (size_t)TT * BB * LL + (size_t)TT * BB;
        out[base + i] = hfin[i];
        out[base + (size_t)BB * HH + i] = cfin[i];
    }
}

// ---------------- launch ----------------
extern "C" void kernel_launch(void* const* d_in, const int* in_sizes, int n_in,
                              void* d_out, int out_size) {
    (void)out_size;

    // real device addresses of __device__ globals (host shadows are not device ptrs)
    float *p_eg, *p_ep, *p_x, *p_h0, *p_h1, *p_c0, *p_c1;
    cudaGetSymbolAddress((void**)&p_eg, d_eg);
    cudaGetSymbolAddress((void**)&p_ep, d_ep);
    cudaGetSymbolAddress((void**)&p_x, d_x);
    cudaGetSymbolAddress((void**)&p_h0, d_h0b);
    cudaGetSymbolAddress((void**)&p_h1, d_h1b);
    cudaGetSymbolAddress((void**)&p_c0, d_c0b);
    cudaGetSymbolAddress((void**)&p_c1, d_c1b);

    // input-order detection: dict order (expected) vs alphabetical fallback
    static const int sig_dict[19] = {131072, 13107200, 131072, 131072, 13107200,
                                     262144, 1024, 262144, 1024, 65536, 256,
                                     65536, 256, 256, 65536, 256, 65536, 256, 256};
    static const int alpha_map[19] = {6, 7, 13, 4, 5, 1, 3, 0, 2, 8, 10, 9, 11, 12, 14, 16, 15, 17, 18};
    bool dict_ok = (n_in == 19);
    if (dict_ok) for (int i = 0; i < 19; i++) if (in_sizes[i] != sig_dict[i]) { dict_ok = false; break; }
    const float* in[19];
    for (int i = 0; i < 19; i++)
        in[i] = (const float*)d_in[dict_ok ? i : alpha_map[i]];

    const float* dec   = in[0];
    const float* emb   = in[1];
    const float* h0    = in[2];
    const float* c0    = in[3];
    const float* ctx   = in[4];
    const float* Wi    = in[5];
    const float* bi    = in[6];
    const float* Wh    = in[7];
    const float* bh    = in[8];
    const float* gWq   = in[9];
    const float* gbq   = in[10];
    const float* gWref = in[11];
    const float* gbref = in[12];
    const float* gv    = in[13];
    const float* pWq   = in[14];
    const float* pbq   = in[15];
    const float* pWref = in[16];
    const float* pbref = in[17];
    const float* pv    = in[18];

    float* out = (float*)d_out;
    float* out_probs = out;                               // T*B*L
    float* out_sel   = out + (size_t)TT * BB * LL;        // T*B

    init_kernel<<<(BB * EE + 255) / 256, 256>>>(dec, h0, c0);

    // one-time: e_g / e_p  (M=51200, N=256, K=256)
    {
        ACtx a{ctx};
        WDirect wg{gWref, HH};
        gemm_kernel<64, 64, 16, 4, 4><<<dim3(BB * LL / 64, HH / 64), 256>>>(
            a, wg, gbref, p_eg, BB * LL, HH, HH);
        WDirect wp{pWref, HH};
        gemm_kernel<64, 64, 16, 4, 4><<<dim3(BB * LL / 64, HH / 64), 256>>>(
            a, wp, pbref, p_ep, BB * LL, HH, HH);
    }

    for (int t = 0; t < TT; t++) {
        const float* h_in = (t & 1) ? p_h1 : p_h0;
        const float* c_in = (t & 1) ? p_c1 : p_c0;
        float* h_out = (t & 1) ? p_h0 : p_h1;
        float* c_out = (t & 1) ? p_c0 : p_c1;

        gates_lstm_kernel<<<dim3(BB / 32, NG / 64), 256>>>(
            p_x, h_in, Wi, Wh, bi, bh, c_in, c_out, h_out);

        attn_kernel<<<BB, 256>>>(t, h_out, gWq, gbq, gv, pWq, pbq, pv,
                                 emb, out_probs, out_sel, p_x);
    }

    // t=99 (odd) wrote into buffer 0
    finalize_kernel<<<(BB * HH + 255) / 256, 256>>>(p_h0, p_c0, out);
}